// round 5
// baseline (speedup 1.0000x reference)
#include <cuda_runtime.h>

#define BB 128
typedef unsigned long long u64;

__device__ __forceinline__ u64 pack2(float x, float y){
    u64 r; asm("mov.b64 %0,{%1,%2};" : "=l"(r) : "f"(x), "f"(y)); return r;
}
__device__ __forceinline__ void unpack2(u64 a, float& x, float& y){
    asm("mov.b64 {%0,%1},%2;" : "=f"(x), "=f"(y) : "l"(a));
}
__device__ __forceinline__ u64 fma2(u64 a, u64 b, u64 c){
    u64 d; asm("fma.rn.f32x2 %0,%1,%2,%3;" : "=l"(d) : "l"(a), "l"(b), "l"(c)); return d;
}
__device__ __forceinline__ float fast_tanh(float x){
    float e = __expf(2.0f * x);
    return 1.0f - __fdividef(2.0f, e + 1.0f);
}

#define ST_T16 20   // [K][16] transposed tiles (floats)
#define ST_T32 36   // [K][32] transposed tiles
#define ST_RM  132  // row-major [16][128] tile
#define ST_PX  66   // row-major [R][64] tiles (P, X, u, v)

struct Smem {
    float sT    [128 * ST_T16];  // states^T
    float oaoT  [136 * ST_T32];  // [states_o | actions_o]^T
    float act   [16 * 8];
    float pol   [16 * 8];
    float kkT   [128 * ST_T16];
    float qqT   [128 * ST_T16];
    float qoT   [128 * ST_T16];
    float t     [16 * ST_RM];    // states @ Wv[:128], row-major
    float koT   [128 * ST_T32];
    float avoT  [128 * ST_T32];  // tanh(oao @ Wvo), transposed
    float avactT[128 * ST_T16];
    float deltaT[128 * ST_T16];
    float w     [256];
    float wo    [512];
    float P     [16 * ST_PX];    // avact @ W1a
    float X     [32 * ST_PX];    // avo   @ W1b
    float u     [16 * ST_PX];
    float v     [16 * ST_PX];    // delta @ W1a
    float w2    [64];
};

__global__ __launch_bounds__(512, 1)
void critic_kernel(const float* __restrict__ states,
                   const float* __restrict__ policies,
                   const float* __restrict__ actions,
                   const float* __restrict__ states_o,
                   const float* __restrict__ actions_o,
                   const float* __restrict__ Wk,  const float* __restrict__ Wq,
                   const float* __restrict__ Wv,  const float* __restrict__ Wko,
                   const float* __restrict__ Wqo, const float* __restrict__ Wvo,
                   const float* __restrict__ W1,  const float* __restrict__ W2,
                   float* __restrict__ out_value,
                   float* __restrict__ out_w,
                   float* __restrict__ out_wo)
{
    extern __shared__ unsigned char smem_raw[];
    Smem& sm = *reinterpret_cast<Smem*>(smem_raw);

    const int b    = blockIdx.x;
    const int tid  = threadIdx.x;
    const int warp = tid >> 5;
    const int lane = tid & 31;

    // ---------- Stage-1 config (needed early for pre-barrier prefetch) ----------
    int mat, r0, koff, astride;
    const float* Wm;
    const float* Abase;
    if (warp < 8) {
        mat = warp & 3; r0 = (warp >> 2) * 8; koff = warp * 16;
        Wm  = (mat == 0 ? Wk : mat == 1 ? Wq : mat == 2 ? Wqo : Wv) + lane * 4;
        Abase = sm.sT; astride = ST_T16;
    } else {
        const int wrp = warp - 8;
        mat = 4 + (wrp & 1); r0 = (wrp >> 1) * 8; koff = (wrp * 16 + 8) & 127;
        Wm  = ((wrp & 1) ? Wvo : Wko) + lane * 4;
        Abase = sm.oaoT; astride = ST_T32;
    }
    auto ldw = [&](int k){ return *reinterpret_cast<const float4*>(Wm + k * 128); };

    // ---------- Stage 0: load + transpose inputs ----------
    {
        const int k  = tid & 127;
        const int g  = tid >> 7;       // 0..3
        const int rr = g * 4;
        const float* S = states + (size_t)b * 16 * 128;
        {
            float a0 = S[(rr + 0) * 128 + k];
            float a1 = S[(rr + 1) * 128 + k];
            float a2 = S[(rr + 2) * 128 + k];
            float a3 = S[(rr + 3) * 128 + k];
            *reinterpret_cast<float4*>(&sm.sT[k * ST_T16 + rr]) = make_float4(a0, a1, a2, a3);
        }
        const float* SO = states_o + (size_t)b * 32 * 128;
#pragma unroll
        for (int h = 0; h < 32; h += 16) {
            float a0 = SO[(rr + h + 0) * 128 + k];
            float a1 = SO[(rr + h + 1) * 128 + k];
            float a2 = SO[(rr + h + 2) * 128 + k];
            float a3 = SO[(rr + h + 3) * 128 + k];
            *reinterpret_cast<float4*>(&sm.oaoT[k * ST_T32 + rr + h]) = make_float4(a0, a1, a2, a3);
        }
        if (tid < 256) {
            int kk8 = tid >> 5, m = tid & 31;
            sm.oaoT[(128 + kk8) * ST_T32 + m] = actions_o[(size_t)b * 32 * 8 + m * 8 + kk8];
        }
        if (tid < 128) {
            int r = tid >> 3, c = tid & 7;
            sm.act[r * 8 + c] = actions[(size_t)b * 16 * 8 + r * 8 + c];
            sm.pol[r * 8 + c] = policies[(size_t)b * 16 * 8 + r * 8 + c];
        }
        if (tid < 64) sm.w2[tid] = W2[tid];
    }

    // Prefetch first weight group BEFORE the barrier: barrier hides cold L2 latency
    float4 wA = ldw(koff), wB = ldw(koff + 1), wC = ldw(koff + 2), wD = ldw(koff + 3);

    __syncthreads();

    // ---------- Stage 1: projection GEMMs (prefetched, skewed, f32x2) ----------
    {
        u64 acc[4][4];
#pragma unroll
        for (int j = 0; j < 4; j++)
#pragma unroll
            for (int p = 0; p < 4; p++) acc[j][p] = 0ull;

        auto step = [&](int k, float4 w4) {
            const float* Ak = Abase + k * astride + r0;
            const ulonglong2 A0 = *reinterpret_cast<const ulonglong2*>(Ak);
            const ulonglong2 A1 = *reinterpret_cast<const ulonglong2*>(Ak + 4);
            const u64 wp0 = pack2(w4.x, w4.x);
            const u64 wp1 = pack2(w4.y, w4.y);
            const u64 wp2 = pack2(w4.z, w4.z);
            const u64 wp3 = pack2(w4.w, w4.w);
            acc[0][0] = fma2(A0.x, wp0, acc[0][0]);
            acc[0][1] = fma2(A0.y, wp0, acc[0][1]);
            acc[0][2] = fma2(A1.x, wp0, acc[0][2]);
            acc[0][3] = fma2(A1.y, wp0, acc[0][3]);
            acc[1][0] = fma2(A0.x, wp1, acc[1][0]);
            acc[1][1] = fma2(A0.y, wp1, acc[1][1]);
            acc[1][2] = fma2(A1.x, wp1, acc[1][2]);
            acc[1][3] = fma2(A1.y, wp1, acc[1][3]);
            acc[2][0] = fma2(A0.x, wp2, acc[2][0]);
            acc[2][1] = fma2(A0.y, wp2, acc[2][1]);
            acc[2][2] = fma2(A1.x, wp2, acc[2][2]);
            acc[2][3] = fma2(A1.y, wp2, acc[2][3]);
            acc[3][0] = fma2(A0.x, wp3, acc[3][0]);
            acc[3][1] = fma2(A0.y, wp3, acc[3][1]);
            acc[3][2] = fma2(A1.x, wp3, acc[3][2]);
            acc[3][3] = fma2(A1.y, wp3, acc[3][3]);
        };

        int kb = koff;
#pragma unroll 1
        for (int g = 0; g < 32; g++) {
            int kn = kb + 4; kn = (kn >= 128) ? 0 : kn;
            const float4 c0 = wA, c1 = wB, c2 = wC, c3 = wD;
            wA = ldw(kn); wB = ldw(kn + 1); wC = ldw(kn + 2); wD = ldw(kn + 3);
            step(kb + 0, c0);
            step(kb + 1, c1);
            step(kb + 2, c2);
            step(kb + 3, c3);
            kb = kn;
        }

        const int col = lane * 4;
        if (mat < 3) {
            float* oT = (mat == 0 ? sm.kkT : mat == 1 ? sm.qqT : sm.qoT);
#pragma unroll
            for (int j = 0; j < 4; j++) {
                float* d = oT + (col + j) * ST_T16 + r0;
                ulonglong2 s0 = {acc[j][0], acc[j][1]};
                ulonglong2 s1 = {acc[j][2], acc[j][3]};
                *reinterpret_cast<ulonglong2*>(d)     = s0;
                *reinterpret_cast<ulonglong2*>(d + 4) = s1;
            }
        } else if (mat == 3) {
#pragma unroll
            for (int p = 0; p < 4; p++) {
                float x0, y0, x1, y1, x2, y2, x3, y3;
                unpack2(acc[0][p], x0, y0);
                unpack2(acc[1][p], x1, y1);
                unpack2(acc[2][p], x2, y2);
                unpack2(acc[3][p], x3, y3);
                *reinterpret_cast<float4*>(&sm.t[(r0 + 2 * p + 0) * ST_RM + col]) = make_float4(x0, x1, x2, x3);
                *reinterpret_cast<float4*>(&sm.t[(r0 + 2 * p + 1) * ST_RM + col]) = make_float4(y0, y1, y2, y3);
            }
        } else if (mat == 4) {
#pragma unroll
            for (int j = 0; j < 4; j++) {
                float* d = sm.koT + (col + j) * ST_T32 + r0;
                ulonglong2 s0 = {acc[j][0], acc[j][1]};
                ulonglong2 s1 = {acc[j][2], acc[j][3]};
                *reinterpret_cast<ulonglong2*>(d)     = s0;
                *reinterpret_cast<ulonglong2*>(d + 4) = s1;
            }
        } else {
            // Wvo tail: K 128..135 (actions_other)
#pragma unroll
            for (int k = 128; k < 136; k++) step(k, ldw(k));
#pragma unroll
            for (int j = 0; j < 4; j++) {
                float t0, t1, t2, t3, t4, t5, t6, t7;
                unpack2(acc[j][0], t0, t1);
                unpack2(acc[j][1], t2, t3);
                unpack2(acc[j][2], t4, t5);
                unpack2(acc[j][3], t6, t7);
                float* d = sm.avoT + (col + j) * ST_T32 + r0;
                *reinterpret_cast<float4*>(d)     = make_float4(fast_tanh(t0), fast_tanh(t1), fast_tanh(t2), fast_tanh(t3));
                *reinterpret_cast<float4*>(d + 4) = make_float4(fast_tanh(t4), fast_tanh(t5), fast_tanh(t6), fast_tanh(t7));
            }
        }
    }
    __syncthreads();

    // ---------- Stage 2: avactT/deltaT tails + attention scores (f32x2 over j) ----------
    {
        const int g  = tid >> 7;    // 0..3
        const int c  = tid & 127;
        const int rr = g * 4;
        float aa[4], ap[4];
#pragma unroll
        for (int i = 0; i < 4; i++) {
            float tv = sm.t[(rr + i) * ST_RM + c];
            aa[i] = tv; ap[i] = tv;
        }
#pragma unroll
        for (int k = 0; k < 8; k++) {
            float wv = Wv[(128 + k) * 128 + c];
#pragma unroll
            for (int i = 0; i < 4; i++) {
                aa[i] = fmaf(sm.act[(rr + i) * 8 + k], wv, aa[i]);
                ap[i] = fmaf(sm.pol[(rr + i) * 8 + k], wv, ap[i]);
            }
        }
        float ta[4], dl[4];
#pragma unroll
        for (int i = 0; i < 4; i++) {
            ta[i] = fast_tanh(aa[i]);
            dl[i] = fast_tanh(ap[i]) - ta[i];
        }
        *reinterpret_cast<float4*>(&sm.avactT[c * ST_T16 + rr]) = make_float4(ta[0], ta[1], ta[2], ta[3]);
        *reinterpret_cast<float4*>(&sm.deltaT[c * ST_T16 + rr]) = make_float4(dl[0], dl[1], dl[2], dl[3]);
    }
    const float scale = 0.08838834764831845f;  // 1/sqrt(128)
    if (tid < 128) {
        // w scores: thread -> (i, j-pair)
        const int i = tid >> 3, j2 = tid & 7;
        u64 a0 = 0ull, a1 = 0ull;
#pragma unroll 4
        for (int k = 0; k < 128; k += 2) {
            const float q0 = sm.qqT[(k + 0) * ST_T16 + i];
            const float q1 = sm.qqT[(k + 1) * ST_T16 + i];
            const u64 kp0 = *reinterpret_cast<const u64*>(&sm.kkT[(k + 0) * ST_T16 + 2 * j2]);
            const u64 kp1 = *reinterpret_cast<const u64*>(&sm.kkT[(k + 1) * ST_T16 + 2 * j2]);
            a0 = fma2(pack2(q0, q0), kp0, a0);
            a1 = fma2(pack2(q1, q1), kp1, a1);
        }
        float s0, s1, t0, t1;
        unpack2(a0, s0, s1);
        unpack2(a1, t0, t1);
        *reinterpret_cast<float2*>(&sm.w[i * 16 + 2 * j2]) =
            make_float2((s0 + t0) * scale, (s1 + t1) * scale);
    } else if (tid < 384) {
        // wo scores: thread -> (i, m-pair)
        const int t2 = tid - 128;
        const int i = t2 >> 4, m2 = t2 & 15;
        u64 a0 = 0ull, a1 = 0ull;
#pragma unroll 4
        for (int k = 0; k < 128; k += 2) {
            const float q0 = sm.qoT[(k + 0) * ST_T16 + i];
            const float q1 = sm.qoT[(k + 1) * ST_T16 + i];
            const u64 kp0 = *reinterpret_cast<const u64*>(&sm.koT[(k + 0) * ST_T32 + 2 * m2]);
            const u64 kp1 = *reinterpret_cast<const u64*>(&sm.koT[(k + 1) * ST_T32 + 2 * m2]);
            a0 = fma2(pack2(q0, q0), kp0, a0);
            a1 = fma2(pack2(q1, q1), kp1, a1);
        }
        float s0, s1, t0, t1;
        unpack2(a0, s0, s1);
        unpack2(a1, t0, t1);
        *reinterpret_cast<float2*>(&sm.wo[i * 32 + 2 * m2]) =
            make_float2((s0 + t0) * scale, (s1 + t1) * scale);
    }

    // ---------- Stage-3 config + prefetch (before barrier) ----------
    const float* AT;
    const float* Wg;
    float* dst3;
    int r03, strideA3, col3;
    if (tid < 256) {
        const int cq2 = tid & 31;
        const int rg  = tid >> 5;
        col3 = cq2 * 2;
        AT   = (rg < 4 ? sm.avactT : sm.deltaT);
        r03  = (rg & 3) * 4;
        strideA3 = ST_T16;
        Wg   = W1;
        dst3 = (rg < 4 ? sm.P : sm.v);
    } else {
        const int tid2 = tid - 256;
        const int cq2 = tid2 & 31;
        const int rg  = tid2 >> 5;
        col3 = cq2 * 2;
        AT   = sm.avoT;
        r03  = rg * 4;
        strideA3 = ST_T32;
        Wg   = W1 + 128 * 64;
        dst3 = sm.X;
    }
    const int koff3 = ((tid >> 5) & 7) * 16;
    auto ldw3 = [&](int k){ return *reinterpret_cast<const float2*>(Wg + k * 64 + col3); };
    float2 pA = ldw3(koff3), pB = ldw3(koff3 + 1), pC = ldw3(koff3 + 2), pD = ldw3(koff3 + 3);

    __syncthreads();

    // ---------- Stage 3: softmaxes (few threads) + P/v/X GEMMs (all) ----------
    if (tid < 16) {
        const int i = tid;
        float mx = -1e30f;
#pragma unroll
        for (int j = 0; j < 16; j++) mx = fmaxf(mx, sm.w[i * 16 + j]);
        float s = 0.f, e[16];
#pragma unroll
        for (int j = 0; j < 16; j++) { e[j] = __expf(sm.w[i * 16 + j] - mx); s += e[j]; }
        const float inv = __fdividef(1.f, s);
#pragma unroll
        for (int j = 0; j < 16; j++) {
            float p = e[j] * inv;
            sm.w[i * 16 + j] = p;
            out_w[(size_t)b * 256 + i * 16 + j] = p;
        }
    } else if (tid < 48) {
        const int m = tid - 16;
        float mx = -1e30f;
#pragma unroll
        for (int i = 0; i < 16; i++) mx = fmaxf(mx, sm.wo[i * 32 + m]);
        float s = 0.f, e[16];
#pragma unroll
        for (int i = 0; i < 16; i++) { e[i] = __expf(sm.wo[i * 32 + m] - mx); s += e[i]; }
        const float inv = __fdividef(1.f, s);
#pragma unroll
        for (int i = 0; i < 16; i++) {
            float p = e[i] * inv;
            sm.wo[i * 32 + m] = p;
            out_wo[(size_t)b * 512 + i * 32 + m] = p;
        }
    }
    // P = avact @ W1a, v = delta @ W1a, X = avo @ W1b
    {
        u64 a00 = 0ull, a01 = 0ull, a10 = 0ull, a11 = 0ull;
        auto step3 = [&](int k, float2 wv) {
            const ulonglong2 A = *reinterpret_cast<const ulonglong2*>(&AT[k * strideA3 + r03]);
            const u64 wp0 = pack2(wv.x, wv.x);
            const u64 wp1 = pack2(wv.y, wv.y);
            a00 = fma2(A.x, wp0, a00);
            a01 = fma2(A.y, wp0, a01);
            a10 = fma2(A.x, wp1, a10);
            a11 = fma2(A.y, wp1, a11);
        };
        int kb = koff3;
#pragma unroll 1
        for (int g = 0; g < 32; g++) {
            int kn = kb + 4; kn = (kn >= 128) ? 0 : kn;
            const float2 c0 = pA, c1 = pB, c2 = pC, c3 = pD;
            pA = ldw3(kn); pB = ldw3(kn + 1); pC = ldw3(kn + 2); pD = ldw3(kn + 3);
            step3(kb + 0, c0);
            step3(kb + 1, c1);
            step3(kb + 2, c2);
            step3(kb + 3, c3);
            kb = kn;
        }
        float x0, x1, x2, x3, y0, y1, y2, y3;
        unpack2(a00, x0, x1); unpack2(a01, x2, x3);
        unpack2(a10, y0, y1); unpack2(a11, y2, y3);
        *reinterpret_cast<float2*>(&dst3[(r03 + 0) * ST_PX + col3]) = make_float2(x0, y0);
        *reinterpret_cast<float2*>(&dst3[(r03 + 1) * ST_PX + col3]) = make_float2(x1, y1);
        *reinterpret_cast<float2*>(&dst3[(r03 + 2) * ST_PX + col3]) = make_float2(x2, y2);
        *reinterpret_cast<float2*>(&dst3[(r03 + 3) * ST_PX + col3]) = make_float2(x3, y3);
    }
    __syncthreads();

    // ---------- Stage 5: u = w @ P + wo @ X ----------
    {
        const int i = tid >> 5;
        const int c = (tid & 31) * 2;
        float acc0 = 0.f, acc1 = 0.f, bcc0 = 0.f, bcc1 = 0.f;
#pragma unroll
        for (int j = 0; j < 16; j += 2) {
            const float wv0 = sm.w[i * 16 + j];
            const float wv1 = sm.w[i * 16 + j + 1];
            const float2 p0 = *reinterpret_cast<const float2*>(&sm.P[j * ST_PX + c]);
            const float2 p1 = *reinterpret_cast<const float2*>(&sm.P[(j + 1) * ST_PX + c]);
            acc0 = fmaf(wv0, p0.x, acc0);
            acc1 = fmaf(wv0, p0.y, acc1);
            bcc0 = fmaf(wv1, p1.x, bcc0);
            bcc1 = fmaf(wv1, p1.y, bcc1);
        }
#pragma unroll
        for (int m = 0; m < 32; m += 2) {
            const float wv0 = sm.wo[i * 32 + m];
            const float wv1 = sm.wo[i * 32 + m + 1];
            const float2 x0 = *reinterpret_cast<const float2*>(&sm.X[m * ST_PX + c]);
            const float2 x1 = *reinterpret_cast<const float2*>(&sm.X[(m + 1) * ST_PX + c]);
            acc0 = fmaf(wv0, x0.x, acc0);
            acc1 = fmaf(wv0, x0.y, acc1);
            bcc0 = fmaf(wv1, x1.x, bcc0);
            bcc1 = fmaf(wv1, x1.y, bcc1);
        }
        *reinterpret_cast<float2*>(&sm.u[i * ST_PX + c]) = make_float2(acc0 + bcc0, acc1 + bcc1);
    }
    __syncthreads();

    // ---------- Stage 6: final value ----------
    {
        const int p = tid >> 1, h = tid & 1;
        const int i = p >> 4, j = p & 15;
        const float wt = sm.w[i * 16 + j];
        float acc0 = 0.f, acc1 = 0.f;
        const int d0 = h * 32;
#pragma unroll
        for (int d = d0; d < d0 + 32; d += 2) {
            float h0 = fmaf(wt, sm.v[j * ST_PX + d],     sm.u[i * ST_PX + d]);
            float h1 = fmaf(wt, sm.v[j * ST_PX + d + 1], sm.u[i * ST_PX + d + 1]);
            h0 = fmaxf(h0, 0.01f * h0);
            h1 = fmaxf(h1, 0.01f * h1);
            acc0 = fmaf(h0, sm.w2[d],     acc0);
            acc1 = fmaf(h1, sm.w2[d + 1], acc1);
        }
        float acc = acc0 + acc1;
        acc += __shfl_xor_sync(0xffffffffu, acc, 1);
        if (h == 0) out_value[(size_t)b * 256 + p] = acc;
    }
}

extern "C" void kernel_launch(void* const* d_in, const int* in_sizes, int n_in,
                              void* d_out, int out_size) {
    const float* states    = (const float*)d_in[0];
    const float* policies  = (const float*)d_in[1];
    const float* actions   = (const float*)d_in[2];
    const float* states_o  = (const float*)d_in[3];
    const float* actions_o = (const float*)d_in[4];
    const float* Wk  = (const float*)d_in[5];
    const float* Wq  = (const float*)d_in[6];
    const float* Wv  = (const float*)d_in[7];
    const float* Wko = (const float*)d_in[8];
    const float* Wqo = (const float*)d_in[9];
    const float* Wvo = (const float*)d_in[10];
    const float* W1  = (const float*)d_in[11];
    const float* W2  = (const float*)d_in[12];

    float* out       = (float*)d_out;
    float* out_value = out;                    // [B,N,N,1]
    float* out_w     = out + BB * 256;         // [B,N,N]
    float* out_wo    = out + 2 * BB * 256;     // [B,N,M,1]

    cudaFuncSetAttribute(critic_kernel,
                         cudaFuncAttributeMaxDynamicSharedMemorySize,
                         (int)sizeof(Smem));

    critic_kernel<<<BB, 512, sizeof(Smem)>>>(states, policies, actions,
                                             states_o, actions_o,
                                             Wk, Wq, Wv, Wko, Wqo, Wvo, W1, W2,
                                             out_value, out_w, out_wo);
}

// round 6
// speedup vs baseline: 1.0702x; 1.0702x over previous
#include <cuda_runtime.h>

#define BB 128
typedef unsigned long long u64;

__device__ __forceinline__ u64 pack2(float x, float y){
    u64 r; asm("mov.b64 %0,{%1,%2};" : "=l"(r) : "f"(x), "f"(y)); return r;
}
__device__ __forceinline__ void unpack2(u64 a, float& x, float& y){
    asm("mov.b64 {%0,%1},%2;" : "=f"(x), "=f"(y) : "l"(a));
}
__device__ __forceinline__ u64 fma2(u64 a, u64 b, u64 c){
    u64 d; asm("fma.rn.f32x2 %0,%1,%2,%3;" : "=l"(d) : "l"(a), "l"(b), "l"(c)); return d;
}
__device__ __forceinline__ float fast_tanh(float x){
    float e = __expf(2.0f * x);
    return 1.0f - __fdividef(2.0f, e + 1.0f);
}

#define ST_T16 20   // [K][16] transposed tiles (floats)
#define ST_T32 36   // [K][32] transposed tiles
#define ST_RM  132  // row-major [16][128] tile
#define ST_PX  66   // row-major [R][64] tiles (P, X, u, v)

struct Smem {
    float sT    [128 * ST_T16];  // states^T
    float oaoT  [136 * ST_T32];  // [states_o | actions_o]^T
    float act   [16 * 8];
    float pol   [16 * 8];
    float kkT   [128 * ST_T16];
    float qqT   [128 * ST_T16];
    float qoT   [128 * ST_T16];
    float t     [16 * ST_RM];    // states @ Wv[:128], row-major
    float koT   [128 * ST_T32];
    float avoT  [128 * ST_T32];  // tanh(oao @ Wvo), transposed
    float avactT[128 * ST_T16];
    float deltaT[128 * ST_T16];
    float w     [256];
    float wo    [512];
    float P     [16 * ST_PX];    // avact @ W1a
    float X     [32 * ST_PX];    // avo   @ W1b
    float u     [16 * ST_PX];
    float v     [16 * ST_PX];    // delta @ W1a
    float w2    [64];
};

__global__ __launch_bounds__(512, 1)
void critic_kernel(const float* __restrict__ states,
                   const float* __restrict__ policies,
                   const float* __restrict__ actions,
                   const float* __restrict__ states_o,
                   const float* __restrict__ actions_o,
                   const float* __restrict__ Wk,  const float* __restrict__ Wq,
                   const float* __restrict__ Wv,  const float* __restrict__ Wko,
                   const float* __restrict__ Wqo, const float* __restrict__ Wvo,
                   const float* __restrict__ W1,  const float* __restrict__ W2,
                   float* __restrict__ out_value,
                   float* __restrict__ out_w,
                   float* __restrict__ out_wo)
{
    extern __shared__ unsigned char smem_raw[];
    Smem& sm = *reinterpret_cast<Smem*>(smem_raw);

    const int b    = blockIdx.x;
    const int tid  = threadIdx.x;
    const int warp = tid >> 5;
    const int lane = tid & 31;

    // ---------- Stage-1 config: COLUMN-split, RB = all rows ----------
    // warps 0-7 : mat = warp>>1 in {Wk,Wq,Wqo,Wv}, col-half = warp&1, rows 0..15 of sT.
    //             each weight matrix byte is loaded exactly ONCE.
    // warps 8-15: mat = Wko/Wvo (wrp>>2), row-half = (wrp>>1)&1, col-half = wrp&1.
    //             each weight matrix byte loaded twice (two row-half warps).
    int mat, r0, koff, astride, col;
    const float* Wm;
    const float* Abase;
    if (warp < 8) {
        mat = warp >> 1;
        r0 = 0; astride = ST_T16;
        koff = warp * 16;
        col = (warp & 1) * 64 + lane * 2;
        Wm  = (mat == 0 ? Wk : mat == 1 ? Wq : mat == 2 ? Wqo : Wv) + col;
        Abase = sm.sT;
    } else {
        const int wrp = warp - 8;
        mat = 4 + (wrp >> 2);
        r0 = ((wrp >> 1) & 1) * 16; astride = ST_T32;
        koff = (wrp * 16 + 8) & 127;
        col = (wrp & 1) * 64 + lane * 2;
        Wm  = (mat == 5 ? Wvo : Wko) + col;
        Abase = sm.oaoT;
    }
    auto ldw = [&](int k){ return *reinterpret_cast<const float2*>(Wm + k * 128); };

    // ---------- Stage 0: load + transpose inputs ----------
    {
        const int k  = tid & 127;
        const int g  = tid >> 7;       // 0..3
        const int rr = g * 4;
        const float* S = states + (size_t)b * 16 * 128;
        {
            float a0 = S[(rr + 0) * 128 + k];
            float a1 = S[(rr + 1) * 128 + k];
            float a2 = S[(rr + 2) * 128 + k];
            float a3 = S[(rr + 3) * 128 + k];
            *reinterpret_cast<float4*>(&sm.sT[k * ST_T16 + rr]) = make_float4(a0, a1, a2, a3);
        }
        const float* SO = states_o + (size_t)b * 32 * 128;
#pragma unroll
        for (int h = 0; h < 32; h += 16) {
            float a0 = SO[(rr + h + 0) * 128 + k];
            float a1 = SO[(rr + h + 1) * 128 + k];
            float a2 = SO[(rr + h + 2) * 128 + k];
            float a3 = SO[(rr + h + 3) * 128 + k];
            *reinterpret_cast<float4*>(&sm.oaoT[k * ST_T32 + rr + h]) = make_float4(a0, a1, a2, a3);
        }
        if (tid < 256) {
            int kk8 = tid >> 5, m = tid & 31;
            sm.oaoT[(128 + kk8) * ST_T32 + m] = actions_o[(size_t)b * 32 * 8 + m * 8 + kk8];
        }
        if (tid < 128) {
            int r = tid >> 3, c = tid & 7;
            sm.act[r * 8 + c] = actions[(size_t)b * 16 * 8 + r * 8 + c];
            sm.pol[r * 8 + c] = policies[(size_t)b * 16 * 8 + r * 8 + c];
        }
        if (tid < 64) sm.w2[tid] = W2[tid];
    }

    // Prefetch first weight group BEFORE the barrier (barrier hides cold L2 latency)
    float2 wA = ldw(koff), wB = ldw(koff + 1), wC = ldw(koff + 2), wD = ldw(koff + 3);

    __syncthreads();

    // ---------- Stage 1: projection GEMMs (col-split, skewed, f32x2) ----------
    {
        u64 acc[2][8];
#pragma unroll
        for (int j = 0; j < 2; j++)
#pragma unroll
            for (int p = 0; p < 8; p++) acc[j][p] = 0ull;

        auto step = [&](int k, float2 w2) {
            const float* Ak = Abase + k * astride + r0;
            const ulonglong2 A0 = *reinterpret_cast<const ulonglong2*>(Ak);
            const ulonglong2 A1 = *reinterpret_cast<const ulonglong2*>(Ak + 4);
            const ulonglong2 A2 = *reinterpret_cast<const ulonglong2*>(Ak + 8);
            const ulonglong2 A3 = *reinterpret_cast<const ulonglong2*>(Ak + 12);
            const u64 wp0 = pack2(w2.x, w2.x);
            const u64 wp1 = pack2(w2.y, w2.y);
            acc[0][0] = fma2(A0.x, wp0, acc[0][0]);
            acc[0][1] = fma2(A0.y, wp0, acc[0][1]);
            acc[0][2] = fma2(A1.x, wp0, acc[0][2]);
            acc[0][3] = fma2(A1.y, wp0, acc[0][3]);
            acc[0][4] = fma2(A2.x, wp0, acc[0][4]);
            acc[0][5] = fma2(A2.y, wp0, acc[0][5]);
            acc[0][6] = fma2(A3.x, wp0, acc[0][6]);
            acc[0][7] = fma2(A3.y, wp0, acc[0][7]);
            acc[1][0] = fma2(A0.x, wp1, acc[1][0]);
            acc[1][1] = fma2(A0.y, wp1, acc[1][1]);
            acc[1][2] = fma2(A1.x, wp1, acc[1][2]);
            acc[1][3] = fma2(A1.y, wp1, acc[1][3]);
            acc[1][4] = fma2(A2.x, wp1, acc[1][4]);
            acc[1][5] = fma2(A2.y, wp1, acc[1][5]);
            acc[1][6] = fma2(A3.x, wp1, acc[1][6]);
            acc[1][7] = fma2(A3.y, wp1, acc[1][7]);
        };

        // peeled prefetched group, then static-address loops (skewed start)
        step(koff + 0, wA);
        step(koff + 1, wB);
        step(koff + 2, wC);
        step(koff + 3, wD);
#pragma unroll 4
        for (int k = koff + 4; k < 128; k++) step(k, ldw(k));
#pragma unroll 4
        for (int k = 0; k < koff; k++) step(k, ldw(k));

        if (mat < 3) {
            float* oT = (mat == 0 ? sm.kkT : mat == 1 ? sm.qqT : sm.qoT);
#pragma unroll
            for (int j = 0; j < 2; j++) {
                float* d = oT + (col + j) * ST_T16;
                ulonglong2 s0 = {acc[j][0], acc[j][1]};
                ulonglong2 s1 = {acc[j][2], acc[j][3]};
                ulonglong2 s2 = {acc[j][4], acc[j][5]};
                ulonglong2 s3 = {acc[j][6], acc[j][7]};
                *reinterpret_cast<ulonglong2*>(d)      = s0;
                *reinterpret_cast<ulonglong2*>(d + 4)  = s1;
                *reinterpret_cast<ulonglong2*>(d + 8)  = s2;
                *reinterpret_cast<ulonglong2*>(d + 12) = s3;
            }
        } else if (mat == 3) {
            // t row-major [16][ST_RM]
#pragma unroll
            for (int p = 0; p < 8; p++) {
                float x0, y0, x1, y1;
                unpack2(acc[0][p], x0, y0);
                unpack2(acc[1][p], x1, y1);
                *reinterpret_cast<float2*>(&sm.t[(2 * p + 0) * ST_RM + col]) = make_float2(x0, x1);
                *reinterpret_cast<float2*>(&sm.t[(2 * p + 1) * ST_RM + col]) = make_float2(y0, y1);
            }
        } else if (mat == 4) {
#pragma unroll
            for (int j = 0; j < 2; j++) {
                float* d = sm.koT + (col + j) * ST_T32 + r0;
                ulonglong2 s0 = {acc[j][0], acc[j][1]};
                ulonglong2 s1 = {acc[j][2], acc[j][3]};
                ulonglong2 s2 = {acc[j][4], acc[j][5]};
                ulonglong2 s3 = {acc[j][6], acc[j][7]};
                *reinterpret_cast<ulonglong2*>(d)      = s0;
                *reinterpret_cast<ulonglong2*>(d + 4)  = s1;
                *reinterpret_cast<ulonglong2*>(d + 8)  = s2;
                *reinterpret_cast<ulonglong2*>(d + 12) = s3;
            }
        } else {
            // Wvo tail: K 128..135 (actions_other), then tanh
#pragma unroll
            for (int k = 128; k < 136; k++) step(k, ldw(k));
#pragma unroll
            for (int j = 0; j < 2; j++) {
                float t0, t1, t2, t3, t4, t5, t6, t7;
                float s0, s1, s2, s3, s4, s5, s6, s7;
                unpack2(acc[j][0], t0, t1);
                unpack2(acc[j][1], t2, t3);
                unpack2(acc[j][2], t4, t5);
                unpack2(acc[j][3], t6, t7);
                unpack2(acc[j][4], s0, s1);
                unpack2(acc[j][5], s2, s3);
                unpack2(acc[j][6], s4, s5);
                unpack2(acc[j][7], s6, s7);
                float* d = sm.avoT + (col + j) * ST_T32 + r0;
                *reinterpret_cast<float4*>(d)      = make_float4(fast_tanh(t0), fast_tanh(t1), fast_tanh(t2), fast_tanh(t3));
                *reinterpret_cast<float4*>(d + 4)  = make_float4(fast_tanh(t4), fast_tanh(t5), fast_tanh(t6), fast_tanh(t7));
                *reinterpret_cast<float4*>(d + 8)  = make_float4(fast_tanh(s0), fast_tanh(s1), fast_tanh(s2), fast_tanh(s3));
                *reinterpret_cast<float4*>(d + 12) = make_float4(fast_tanh(s4), fast_tanh(s5), fast_tanh(s6), fast_tanh(s7));
            }
        }
    }
    __syncthreads();

    // ---------- Stage 2: avactT/deltaT tails + attention scores (f32x2 over j) ----------
    {
        const int g  = tid >> 7;    // 0..3
        const int c  = tid & 127;
        const int rr = g * 4;
        float aa[4], ap[4];
#pragma unroll
        for (int i = 0; i < 4; i++) {
            float tv = sm.t[(rr + i) * ST_RM + c];
            aa[i] = tv; ap[i] = tv;
        }
#pragma unroll
        for (int k = 0; k < 8; k++) {
            float wv = Wv[(128 + k) * 128 + c];
#pragma unroll
            for (int i = 0; i < 4; i++) {
                aa[i] = fmaf(sm.act[(rr + i) * 8 + k], wv, aa[i]);
                ap[i] = fmaf(sm.pol[(rr + i) * 8 + k], wv, ap[i]);
            }
        }
        float ta[4], dl[4];
#pragma unroll
        for (int i = 0; i < 4; i++) {
            ta[i] = fast_tanh(aa[i]);
            dl[i] = fast_tanh(ap[i]) - ta[i];
        }
        *reinterpret_cast<float4*>(&sm.avactT[c * ST_T16 + rr]) = make_float4(ta[0], ta[1], ta[2], ta[3]);
        *reinterpret_cast<float4*>(&sm.deltaT[c * ST_T16 + rr]) = make_float4(dl[0], dl[1], dl[2], dl[3]);
    }
    const float scale = 0.08838834764831845f;  // 1/sqrt(128)
    if (tid < 128) {
        const int i = tid >> 3, j2 = tid & 7;
        u64 a0 = 0ull, a1 = 0ull;
#pragma unroll 4
        for (int k = 0; k < 128; k += 2) {
            const float q0 = sm.qqT[(k + 0) * ST_T16 + i];
            const float q1 = sm.qqT[(k + 1) * ST_T16 + i];
            const u64 kp0 = *reinterpret_cast<const u64*>(&sm.kkT[(k + 0) * ST_T16 + 2 * j2]);
            const u64 kp1 = *reinterpret_cast<const u64*>(&sm.kkT[(k + 1) * ST_T16 + 2 * j2]);
            a0 = fma2(pack2(q0, q0), kp0, a0);
            a1 = fma2(pack2(q1, q1), kp1, a1);
        }
        float s0, s1, t0, t1;
        unpack2(a0, s0, s1);
        unpack2(a1, t0, t1);
        *reinterpret_cast<float2*>(&sm.w[i * 16 + 2 * j2]) =
            make_float2((s0 + t0) * scale, (s1 + t1) * scale);
    } else if (tid < 384) {
        const int t2 = tid - 128;
        const int i = t2 >> 4, m2 = t2 & 15;
        u64 a0 = 0ull, a1 = 0ull;
#pragma unroll 4
        for (int k = 0; k < 128; k += 2) {
            const float q0 = sm.qoT[(k + 0) * ST_T16 + i];
            const float q1 = sm.qoT[(k + 1) * ST_T16 + i];
            const u64 kp0 = *reinterpret_cast<const u64*>(&sm.koT[(k + 0) * ST_T32 + 2 * m2]);
            const u64 kp1 = *reinterpret_cast<const u64*>(&sm.koT[(k + 1) * ST_T32 + 2 * m2]);
            a0 = fma2(pack2(q0, q0), kp0, a0);
            a1 = fma2(pack2(q1, q1), kp1, a1);
        }
        float s0, s1, t0, t1;
        unpack2(a0, s0, s1);
        unpack2(a1, t0, t1);
        *reinterpret_cast<float2*>(&sm.wo[i * 32 + 2 * m2]) =
            make_float2((s0 + t0) * scale, (s1 + t1) * scale);
    }

    // ---------- Stage-3 config + prefetch (before barrier) ----------
    const float* AT;
    const float* Wg;
    float* dst3;
    int r03, strideA3, col3;
    if (tid < 256) {
        const int cq2 = tid & 31;
        const int rg  = tid >> 5;
        col3 = cq2 * 2;
        AT   = (rg < 4 ? sm.avactT : sm.deltaT);
        r03  = (rg & 3) * 4;
        strideA3 = ST_T16;
        Wg   = W1;
        dst3 = (rg < 4 ? sm.P : sm.v);
    } else {
        const int tid2 = tid - 256;
        const int cq2 = tid2 & 31;
        const int rg  = tid2 >> 5;
        col3 = cq2 * 2;
        AT   = sm.avoT;
        r03  = rg * 4;
        strideA3 = ST_T32;
        Wg   = W1 + 128 * 64;
        dst3 = sm.X;
    }
    const int koff3 = ((tid >> 5) & 7) * 16;
    auto ldw3 = [&](int k){ return *reinterpret_cast<const float2*>(Wg + k * 64 + col3); };
    float2 pA = ldw3(koff3), pB = ldw3(koff3 + 1), pC = ldw3(koff3 + 2), pD = ldw3(koff3 + 3);

    __syncthreads();

    // ---------- Stage 3: softmaxes (few threads) + P/v/X GEMMs (all) ----------
    if (tid < 16) {
        const int i = tid;
        float mx = -1e30f;
#pragma unroll
        for (int j = 0; j < 16; j++) mx = fmaxf(mx, sm.w[i * 16 + j]);
        float s = 0.f, e[16];
#pragma unroll
        for (int j = 0; j < 16; j++) { e[j] = __expf(sm.w[i * 16 + j] - mx); s += e[j]; }
        const float inv = __fdividef(1.f, s);
#pragma unroll
        for (int j = 0; j < 16; j++) {
            float p = e[j] * inv;
            sm.w[i * 16 + j] = p;
            out_w[(size_t)b * 256 + i * 16 + j] = p;
        }
    } else if (tid < 48) {
        const int m = tid - 16;
        float mx = -1e30f;
#pragma unroll
        for (int i = 0; i < 16; i++) mx = fmaxf(mx, sm.wo[i * 32 + m]);
        float s = 0.f, e[16];
#pragma unroll
        for (int i = 0; i < 16; i++) { e[i] = __expf(sm.wo[i * 32 + m] - mx); s += e[i]; }
        const float inv = __fdividef(1.f, s);
#pragma unroll
        for (int i = 0; i < 16; i++) {
            float p = e[i] * inv;
            sm.wo[i * 32 + m] = p;
            out_wo[(size_t)b * 512 + i * 32 + m] = p;
        }
    }
    // P = avact @ W1a, v = delta @ W1a, X = avo @ W1b
    {
        u64 a00 = 0ull, a01 = 0ull, a10 = 0ull, a11 = 0ull;
        auto step3 = [&](int k, float2 wv) {
            const ulonglong2 A = *reinterpret_cast<const ulonglong2*>(&AT[k * strideA3 + r03]);
            const u64 wp0 = pack2(wv.x, wv.x);
            const u64 wp1 = pack2(wv.y, wv.y);
            a00 = fma2(A.x, wp0, a00);
            a01 = fma2(A.y, wp0, a01);
            a10 = fma2(A.x, wp1, a10);
            a11 = fma2(A.y, wp1, a11);
        };
        step3(koff3 + 0, pA);
        step3(koff3 + 1, pB);
        step3(koff3 + 2, pC);
        step3(koff3 + 3, pD);
#pragma unroll 4
        for (int k = koff3 + 4; k < 128; k++) step3(k, ldw3(k));
#pragma unroll 4
        for (int k = 0; k < koff3; k++) step3(k, ldw3(k));

        float x0, x1, x2, x3, y0, y1, y2, y3;
        unpack2(a00, x0, x1); unpack2(a01, x2, x3);
        unpack2(a10, y0, y1); unpack2(a11, y2, y3);
        *reinterpret_cast<float2*>(&dst3[(r03 + 0) * ST_PX + col3]) = make_float2(x0, y0);
        *reinterpret_cast<float2*>(&dst3[(r03 + 1) * ST_PX + col3]) = make_float2(x1, y1);
        *reinterpret_cast<float2*>(&dst3[(r03 + 2) * ST_PX + col3]) = make_float2(x2, y2);
        *reinterpret_cast<float2*>(&dst3[(r03 + 3) * ST_PX + col3]) = make_float2(x3, y3);
    }
    __syncthreads();

    // ---------- Stage 5: u = w @ P + wo @ X ----------
    {
        const int i = tid >> 5;
        const int c = (tid & 31) * 2;
        float acc0 = 0.f, acc1 = 0.f, bcc0 = 0.f, bcc1 = 0.f;
#pragma unroll
        for (int j = 0; j < 16; j += 2) {
            const float wv0 = sm.w[i * 16 + j];
            const float wv1 = sm.w[i * 16 + j + 1];
            const float2 p0 = *reinterpret_cast<const float2*>(&sm.P[j * ST_PX + c]);
            const float2 p1 = *reinterpret_cast<const float2*>(&sm.P[(j + 1) * ST_PX + c]);
            acc0 = fmaf(wv0, p0.x, acc0);
            acc1 = fmaf(wv0, p0.y, acc1);
            bcc0 = fmaf(wv1, p1.x, bcc0);
            bcc1 = fmaf(wv1, p1.y, bcc1);
        }
#pragma unroll
        for (int m = 0; m < 32; m += 2) {
            const float wv0 = sm.wo[i * 32 + m];
            const float wv1 = sm.wo[i * 32 + m + 1];
            const float2 x0 = *reinterpret_cast<const float2*>(&sm.X[m * ST_PX + c]);
            const float2 x1 = *reinterpret_cast<const float2*>(&sm.X[(m + 1) * ST_PX + c]);
            acc0 = fmaf(wv0, x0.x, acc0);
            acc1 = fmaf(wv0, x0.y, acc1);
            bcc0 = fmaf(wv1, x1.x, bcc0);
            bcc1 = fmaf(wv1, x1.y, bcc1);
        }
        *reinterpret_cast<float2*>(&sm.u[i * ST_PX + c]) = make_float2(acc0 + bcc0, acc1 + bcc1);
    }
    __syncthreads();

    // ---------- Stage 6: final value ----------
    {
        const int p = tid >> 1, h = tid & 1;
        const int i = p >> 4, j = p & 15;
        const float wt = sm.w[i * 16 + j];
        float acc0 = 0.f, acc1 = 0.f;
        const int d0 = h * 32;
#pragma unroll
        for (int d = d0; d < d0 + 32; d += 2) {
            float h0 = fmaf(wt, sm.v[j * ST_PX + d],     sm.u[i * ST_PX + d]);
            float h1 = fmaf(wt, sm.v[j * ST_PX + d + 1], sm.u[i * ST_PX + d + 1]);
            h0 = fmaxf(h0, 0.01f * h0);
            h1 = fmaxf(h1, 0.01f * h1);
            acc0 = fmaf(h0, sm.w2[d],     acc0);
            acc1 = fmaf(h1, sm.w2[d + 1], acc1);
        }
        float acc = acc0 + acc1;
        acc += __shfl_xor_sync(0xffffffffu, acc, 1);
        if (h == 0) out_value[(size_t)b * 256 + p] = acc;
    }
}

extern "C" void kernel_launch(void* const* d_in, const int* in_sizes, int n_in,
                              void* d_out, int out_size) {
    const float* states    = (const float*)d_in[0];
    const float* policies  = (const float*)d_in[1];
    const float* actions   = (const float*)d_in[2];
    const float* states_o  = (const float*)d_in[3];
    const float* actions_o = (const float*)d_in[4];
    const float* Wk  = (const float*)d_in[5];
    const float* Wq  = (const float*)d_in[6];
    const float* Wv  = (const float*)d_in[7];
    const float* Wko = (const float*)d_in[8];
    const float* Wqo = (const float*)d_in[9];
    const float* Wvo = (const float*)d_in[10];
    const float* W1  = (const float*)d_in[11];
    const float* W2  = (const float*)d_in[12];

    float* out       = (float*)d_out;
    float* out_value = out;                    // [B,N,N,1]
    float* out_w     = out + BB * 256;         // [B,N,N]
    float* out_wo    = out + 2 * BB * 256;     // [B,N,M,1]

    cudaFuncSetAttribute(critic_kernel,
                         cudaFuncAttributeMaxDynamicSharedMemorySize,
                         (int)sizeof(Smem));

    critic_kernel<<<BB, 512, sizeof(Smem)>>>(states, policies, actions,
                                             states_o, actions_o,
                                             Wk, Wq, Wv, Wko, Wqo, Wvo, W1, W2,
                                             out_value, out_w, out_wo);
}